// round 1
// baseline (speedup 1.0000x reference)
#include <cuda_runtime.h>
#include <cstdint>

#define TT 100
#define NPAIR 4950
#define NPAIR_PAD 4952
#define DD 32
#define AA 16
#define BSZ 1024
#define NTHREADS 256
#define MR 4
#define PSTRIDE (NTHREADS*MR)
#define EPAD 33

// pair index table: (i<<8)|j for itertools.combinations order
__device__ __align__(16) int g_pairIJ[NPAIR_PAD];

__global__ void setup_pairs_kernel() {
    int p = blockIdx.x * blockDim.x + threadIdx.x;
    if (p >= NPAIR_PAD) return;
    if (p >= NPAIR) { g_pairIJ[p] = 0; return; }
    float disc = (float)((2*TT-1)*(2*TT-1) - 8*p);
    int i = (int)(((float)(2*TT-1) - sqrtf(disc)) * 0.5f);
    if (i < 0) i = 0;
    if (i > TT-2) i = TT-2;
    // off(i) = number of pairs before row i = i*(2T-1-i)/2
    while (i > 0        && (i*(2*TT-1-i))/2 > p) i--;
    while (i < TT-2     && ((i+1)*(2*TT-1-(i+1)))/2 <= p) i++;
    int off = (i*(2*TT-1-i))/2;
    int j = p - off + i + 1;
    g_pairIJ[p] = (i << 8) | j;
}

__global__ __launch_bounds__(NTHREADS) void afm_kernel(
    const int*   __restrict__ x,
    const float* __restrict__ Emb,
    const float* __restrict__ W,
    const float* __restrict__ b,
    const float* __restrict__ h,
    const float* __restrict__ W1,
    const float* __restrict__ b1,
    const float* __restrict__ W2,
    const float* __restrict__ b2,
    const float* __restrict__ Wf,
    const float* __restrict__ bf,
    float* __restrict__ out)
{
    __shared__ float es[TT * EPAD];                 // embeddings, padded rows
    __shared__ float att[NPAIR];                    // logits, then exp()
    __shared__ __align__(16) unsigned long long Wsm2[DD * (AA/2)]; // W rows as f32x2 pairs
    __shared__ float hsm[AA];
    __shared__ float bsm[AA];
    __shared__ float W1s[DD*16];
    __shared__ float b1s[16];
    __shared__ float W2s[16*8];
    __shared__ float b2s[8];
    __shared__ float Wfs[8];
    __shared__ float red[NTHREADS/32];
    __shared__ float pool8[8][DD];
    __shared__ float poolv[DD];
    __shared__ float o1s[16];
    __shared__ float o2s[8];
    __shared__ float sm_gmax, sm_isum;

    const int tid  = threadIdx.x;
    const int bidx = blockIdx.x;
    const int lane = tid & 31;
    const int wid  = tid >> 5;

    // ---- stage small weights ----
    {
        float2* Wsmf2 = (float2*)Wsm2;
        const float2* Wg = (const float2*)W;
        for (int idx = tid; idx < DD*AA/2; idx += NTHREADS) Wsmf2[idx] = Wg[idx];
        if (tid < AA) { hsm[tid] = h[tid]; bsm[tid] = b[tid]; }
        for (int idx = tid; idx < DD*16; idx += NTHREADS) W1s[idx] = W1[idx];
        if (tid < 16)  b1s[tid] = b1[tid];
        for (int idx = tid; idx < 16*8; idx += NTHREADS) W2s[idx] = W2[idx];
        if (tid < 8)   { b2s[tid] = b2[tid]; Wfs[tid] = Wf[tid]; }
    }

    // ---- gather embeddings for this batch element ----
    for (int idx = tid; idx < TT*DD; idx += NTHREADS) {
        int t = idx >> 5, d = idx & 31;
        int row = x[bidx*TT + t];
        es[t*EPAD + d] = Emb[(size_t)row * DD + d];
    }
    __syncthreads();

    // packed bias (constant across pairs)
    unsigned long long bias2[AA/2];
    #pragma unroll
    for (int q = 0; q < AA/2; q++) {
        float blo = bsm[2*q], bhi = bsm[2*q+1];
        asm("mov.b64 %0, {%1, %2};" : "=l"(bias2[q]) : "f"(blo), "f"(bhi));
    }

    // ================= PASS 1: logits per pair =================
    float lmax = -1e30f;
    for (int p0 = tid*MR; p0 < NPAIR; p0 += PSTRIDE) {
        int4 pv = *((const int4*)&g_pairIJ[p0]);   // padded array: always safe
        int pi[MR], pj[MR];
        pi[0] = pv.x >> 8; pj[0] = pv.x & 255;
        pi[1] = pv.y >> 8; pj[1] = pv.y & 255;
        pi[2] = pv.z >> 8; pj[2] = pv.z & 255;
        pi[3] = pv.w >> 8; pj[3] = pv.w & 255;

        unsigned long long zz[MR][AA/2];
        #pragma unroll
        for (int m = 0; m < MR; m++)
            #pragma unroll
            for (int q = 0; q < AA/2; q++) zz[m][q] = bias2[q];

        #pragma unroll 8
        for (int k = 0; k < DD; k++) {
            // W row k, packed as 8 ull (f32x2 over the A dimension)
            unsigned long long w2[AA/2];
            const ulonglong2* wr = (const ulonglong2*)&Wsm2[k*(AA/2)];
            #pragma unroll
            for (int q2 = 0; q2 < AA/4; q2++) {
                ulonglong2 t2 = wr[q2];
                w2[2*q2] = t2.x; w2[2*q2+1] = t2.y;
            }
            #pragma unroll
            for (int m = 0; m < MR; m++) {
                float pm = es[pi[m]*EPAD + k] * es[pj[m]*EPAD + k];
                unsigned long long pp;
                asm("mov.b64 %0, {%1, %1};" : "=l"(pp) : "f"(pm));
                #pragma unroll
                for (int q = 0; q < AA/2; q++) {
                    asm("fma.rn.f32x2 %0, %1, %2, %0;"
                        : "+l"(zz[m][q]) : "l"(pp), "l"(w2[q]));
                }
            }
        }
        // relu + dot(h) epilogue
        #pragma unroll
        for (int m = 0; m < MR; m++) {
            float logit = 0.f;
            #pragma unroll
            for (int q = 0; q < AA/2; q++) {
                float lo, hi;
                asm("mov.b64 {%0, %1}, %2;" : "=f"(lo), "=f"(hi) : "l"(zz[m][q]));
                logit = fmaf(fmaxf(lo, 0.f), hsm[2*q],   logit);
                logit = fmaf(fmaxf(hi, 0.f), hsm[2*q+1], logit);
            }
            int p = p0 + m;
            if (p < NPAIR) { att[p] = logit; lmax = fmaxf(lmax, logit); }
        }
    }

    // ================= softmax over 4950 logits =================
    #pragma unroll
    for (int o = 16; o > 0; o >>= 1) lmax = fmaxf(lmax, __shfl_xor_sync(0xffffffffu, lmax, o));
    if (lane == 0) red[wid] = lmax;
    __syncthreads();
    if (tid < 32) {
        float v = (tid < NTHREADS/32) ? red[tid] : -1e30f;
        #pragma unroll
        for (int o = 4; o > 0; o >>= 1) v = fmaxf(v, __shfl_xor_sync(0xffffffffu, v, o));
        if (tid == 0) sm_gmax = v;
    }
    __syncthreads();
    const float gmax = sm_gmax;

    float lsum = 0.f;
    for (int p = tid; p < NPAIR; p += NTHREADS) {
        float E = __expf(att[p] - gmax);
        att[p] = E;
        lsum += E;
    }
    #pragma unroll
    for (int o = 16; o > 0; o >>= 1) lsum += __shfl_xor_sync(0xffffffffu, lsum, o);
    if (lane == 0) red[wid] = lsum;
    __syncthreads();
    if (tid == 0) {
        float s = 0.f;
        #pragma unroll
        for (int w = 0; w < NTHREADS/32; w++) s += red[w];
        sm_isum = 1.f / s;
    }
    __syncthreads();
    const float inv = sm_isum;

    // ================= PASS 2: attention-pooled sum =================
    // warp -> pair stripe, lane -> embedding dim
    float pacc = 0.f;
    for (int p = wid; p < NPAIR; p += 8) {
        int v = g_pairIJ[p];
        int i = v >> 8, j = v & 255;
        float a = att[p];
        pacc = fmaf(a * es[i*EPAD + lane], es[j*EPAD + lane], pacc);
    }
    pool8[wid][lane] = pacc;
    __syncthreads();
    if (tid < DD) {
        float s = 0.f;
        #pragma unroll
        for (int w = 0; w < 8; w++) s += pool8[w][tid];
        poolv[tid] = s * inv;
    }
    __syncthreads();

    // ================= tiny MLP =================
    if (tid < 16) {
        float z = b1s[tid];
        #pragma unroll
        for (int d = 0; d < DD; d++) z = fmaf(poolv[d], W1s[d*16 + tid], z);
        o1s[tid] = fmaxf(z, 0.f);
    }
    __syncthreads();
    if (tid < 8) {
        float z = b2s[tid];
        #pragma unroll
        for (int c = 0; c < 16; c++) z = fmaf(o1s[c], W2s[c*8 + tid], z);
        o2s[tid] = fmaxf(z, 0.f);
    }
    __syncthreads();
    if (tid == 0) {
        float z = bf[0];
        #pragma unroll
        for (int c = 0; c < 8; c++) z = fmaf(o2s[c], Wfs[c], z);
        out[bidx] = 1.f / (1.f + __expf(-z));
    }
}

extern "C" void kernel_launch(void* const* d_in, const int* in_sizes, int n_in,
                              void* d_out, int out_size) {
    const int*   x   = (const int*)  d_in[0];
    const float* Emb = (const float*)d_in[1];
    const float* W   = (const float*)d_in[2];
    const float* b   = (const float*)d_in[3];
    const float* h   = (const float*)d_in[4];
    const float* W1  = (const float*)d_in[5];
    const float* b1  = (const float*)d_in[6];
    const float* W2  = (const float*)d_in[7];
    const float* b2  = (const float*)d_in[8];
    const float* Wf  = (const float*)d_in[9];
    const float* bf  = (const float*)d_in[10];
    float* out = (float*)d_out;

    setup_pairs_kernel<<<(NPAIR_PAD + 255)/256, 256>>>();
    afm_kernel<<<BSZ, NTHREADS>>>(x, Emb, W, b, h, W1, b1, W2, b2, Wf, bf, out);
}

// round 2
// speedup vs baseline: 1.2627x; 1.2627x over previous
#include <cuda_runtime.h>
#include <cstdint>

#define TT 100
#define NPAIR 4950
#define NPAIR_PAD 4952
#define DD 32
#define AA 16
#define BSZ 1024
#define NTHREADS 128
#define MR 4
#define PSTRIDE (NTHREADS*MR)
#define EPAD 34

// pair index table: (i<<8)|j for itertools.combinations order
__device__ __align__(16) int g_pairIJ[NPAIR_PAD];

__global__ void setup_pairs_kernel() {
    int p = blockIdx.x * blockDim.x + threadIdx.x;
    if (p >= NPAIR_PAD) return;
    if (p >= NPAIR) { g_pairIJ[p] = 0; return; }
    float disc = (float)((2*TT-1)*(2*TT-1) - 8*p);
    int i = (int)(((float)(2*TT-1) - sqrtf(disc)) * 0.5f);
    if (i < 0) i = 0;
    if (i > TT-2) i = TT-2;
    while (i > 0    && (i*(2*TT-1-i))/2 > p) i--;
    while (i < TT-2 && ((i+1)*(2*TT-1-(i+1)))/2 <= p) i++;
    int off = (i*(2*TT-1-i))/2;
    int j = p - off + i + 1;
    g_pairIJ[p] = (i << 8) | j;
}

__global__ __launch_bounds__(NTHREADS, 3) void afm_kernel(
    const int*   __restrict__ x,
    const float* __restrict__ Emb,
    const float* __restrict__ W,
    const float* __restrict__ b,
    const float* __restrict__ h,
    const float* __restrict__ W1,
    const float* __restrict__ b1,
    const float* __restrict__ W2,
    const float* __restrict__ b2,
    const float* __restrict__ Wf,
    const float* __restrict__ bf,
    float* __restrict__ out)
{
    __shared__ __align__(16) float es[TT * EPAD];   // embeddings, padded rows (float2-friendly)
    __shared__ __align__(16) float att[NPAIR_PAD];  // exp(logit)
    __shared__ __align__(16) unsigned long long Wsm2[DD * (AA/2)]; // W rows as f32x2 pairs
    __shared__ float hsm[AA];
    __shared__ float bsm[AA];
    __shared__ float W1s[DD*16];
    __shared__ float b1s[16];
    __shared__ float W2s[16*8];
    __shared__ float b2s[8];
    __shared__ float Wfs[8];
    __shared__ float red[NTHREADS/32];
    __shared__ float pool4[NTHREADS/32][DD];
    __shared__ float poolv[DD];
    __shared__ float o1s[16];
    __shared__ float o2s[8];
    __shared__ float sm_isum;

    const int tid  = threadIdx.x;
    const int bidx = blockIdx.x;
    const int lane = tid & 31;
    const int wid  = tid >> 5;

    // ---- stage small weights ----
    {
        float2* Wsmf2 = (float2*)Wsm2;
        const float2* Wg = (const float2*)W;
        for (int idx = tid; idx < DD*AA/2; idx += NTHREADS) Wsmf2[idx] = Wg[idx];
        if (tid < AA) { hsm[tid] = h[tid]; bsm[tid] = b[tid]; }
        for (int idx = tid; idx < DD*16; idx += NTHREADS) W1s[idx] = W1[idx];
        if (tid < 16)  b1s[tid] = b1[tid];
        for (int idx = tid; idx < 16*8; idx += NTHREADS) W2s[idx] = W2[idx];
        if (tid < 8)   { b2s[tid] = b2[tid]; Wfs[tid] = Wf[tid]; }
    }

    // ---- gather embeddings for this batch element ----
    for (int idx = tid; idx < TT*DD; idx += NTHREADS) {
        int t = idx >> 5, d = idx & 31;
        int row = x[bidx*TT + t];
        es[t*EPAD + d] = Emb[(size_t)row * DD + d];
    }
    __syncthreads();

    // packed bias (constant across pairs)
    unsigned long long bias2[AA/2];
    #pragma unroll
    for (int q = 0; q < AA/2; q++) {
        float blo = bsm[2*q], bhi = bsm[2*q+1];
        asm("mov.b64 %0, {%1, %2};" : "=l"(bias2[q]) : "f"(blo), "f"(bhi));
    }

    // ================= PASS 1: exp(logit) per pair (no max-sub: logits are O(0.01)) ====
    float lsum = 0.f;
    for (int p0 = tid*MR; p0 < NPAIR; p0 += PSTRIDE) {
        int4 pv = *((const int4*)&g_pairIJ[p0]);   // padded: safe
        int pi[MR], pj[MR];
        pi[0] = pv.x >> 8; pj[0] = pv.x & 255;
        pi[1] = pv.y >> 8; pj[1] = pv.y & 255;
        pi[2] = pv.z >> 8; pj[2] = pv.z & 255;
        pi[3] = pv.w >> 8; pj[3] = pv.w & 255;

        unsigned long long zz[MR][AA/2];
        #pragma unroll
        for (int m = 0; m < MR; m++)
            #pragma unroll
            for (int q = 0; q < AA/2; q++) zz[m][q] = bias2[q];

        #pragma unroll 4
        for (int k = 0; k < DD; k += 2) {
            // es as float2 over k — halves es LDS count
            float2 ei[MR], ej[MR];
            #pragma unroll
            for (int m = 0; m < MR; m++) {
                ei[m] = *(const float2*)&es[pi[m]*EPAD + k];
                ej[m] = *(const float2*)&es[pj[m]*EPAD + k];
            }
            #pragma unroll
            for (int kk = 0; kk < 2; kk++) {
                unsigned long long w2[AA/2];
                const ulonglong2* wr = (const ulonglong2*)&Wsm2[(k+kk)*(AA/2)];
                #pragma unroll
                for (int q2 = 0; q2 < AA/4; q2++) {
                    ulonglong2 t2 = wr[q2];
                    w2[2*q2] = t2.x; w2[2*q2+1] = t2.y;
                }
                #pragma unroll
                for (int m = 0; m < MR; m++) {
                    float pm = kk ? (ei[m].y * ej[m].y) : (ei[m].x * ej[m].x);
                    unsigned long long pp;
                    asm("mov.b64 %0, {%1, %1};" : "=l"(pp) : "f"(pm));
                    #pragma unroll
                    for (int q = 0; q < AA/2; q++) {
                        asm("fma.rn.f32x2 %0, %1, %2, %0;"
                            : "+l"(zz[m][q]) : "l"(pp), "l"(w2[q]));
                    }
                }
            }
        }
        // relu + dot(h) + exp epilogue
        #pragma unroll
        for (int m = 0; m < MR; m++) {
            float logit = 0.f;
            #pragma unroll
            for (int q = 0; q < AA/2; q++) {
                float lo, hi;
                asm("mov.b64 {%0, %1}, %2;" : "=f"(lo), "=f"(hi) : "l"(zz[m][q]));
                logit = fmaf(fmaxf(lo, 0.f), hsm[2*q],   logit);
                logit = fmaf(fmaxf(hi, 0.f), hsm[2*q+1], logit);
            }
            int p = p0 + m;
            if (p < NPAIR) {
                float E = __expf(logit);
                att[p] = E;
                lsum += E;
            }
        }
    }

    // ---- block reduce lsum -> 1/sum ----
    #pragma unroll
    for (int o = 16; o > 0; o >>= 1) lsum += __shfl_xor_sync(0xffffffffu, lsum, o);
    if (lane == 0) red[wid] = lsum;
    __syncthreads();
    if (tid == 0) {
        float s = 0.f;
        #pragma unroll
        for (int w = 0; w < NTHREADS/32; w++) s += red[w];
        sm_isum = 1.f / s;
    }
    if (tid < 2) att[NPAIR + tid] = 0.f;   // pad for the unrolled pass-2 tail
    __syncthreads();
    const float inv = sm_isum;

    // ================= PASS 2: attention-pooled sum =================
    // warp -> 2 consecutive pairs per iteration, lane -> embedding dim
    float pacc = 0.f;
    for (int p = wid*2; p < NPAIR; p += (NTHREADS/32)*2) {
        int2   v2 = *(const int2*)  &g_pairIJ[p];  // padded arrays: safe
        float2 a2 = *(const float2*)&att[p];
        int i0 = v2.x >> 8, j0 = v2.x & 255;
        int i1 = v2.y >> 8, j1 = v2.y & 255;
        pacc = fmaf(a2.x * es[i0*EPAD + lane], es[j0*EPAD + lane], pacc);
        pacc = fmaf(a2.y * es[i1*EPAD + lane], es[j1*EPAD + lane], pacc);
    }
    pool4[wid][lane] = pacc;
    __syncthreads();
    if (tid < DD) {
        float s = 0.f;
        #pragma unroll
        for (int w = 0; w < NTHREADS/32; w++) s += pool4[w][tid];
        poolv[tid] = s * inv;
    }
    __syncthreads();

    // ================= tiny MLP =================
    if (tid < 16) {
        float z = b1s[tid];
        #pragma unroll
        for (int d = 0; d < DD; d++) z = fmaf(poolv[d], W1s[d*16 + tid], z);
        o1s[tid] = fmaxf(z, 0.f);
    }
    __syncthreads();
    if (tid < 8) {
        float z = b2s[tid];
        #pragma unroll
        for (int c = 0; c < 16; c++) z = fmaf(o1s[c], W2s[c*8 + tid], z);
        o2s[tid] = fmaxf(z, 0.f);
    }
    __syncthreads();
    if (tid == 0) {
        float z = bf[0];
        #pragma unroll
        for (int c = 0; c < 8; c++) z = fmaf(o2s[c], Wfs[c], z);
        out[bidx] = 1.f / (1.f + __expf(-z));
    }
}

extern "C" void kernel_launch(void* const* d_in, const int* in_sizes, int n_in,
                              void* d_out, int out_size) {
    const int*   x   = (const int*)  d_in[0];
    const float* Emb = (const float*)d_in[1];
    const float* W   = (const float*)d_in[2];
    const float* b   = (const float*)d_in[3];
    const float* h   = (const float*)d_in[4];
    const float* W1  = (const float*)d_in[5];
    const float* b1  = (const float*)d_in[6];
    const float* W2  = (const float*)d_in[7];
    const float* b2  = (const float*)d_in[8];
    const float* Wf  = (const float*)d_in[9];
    const float* bf  = (const float*)d_in[10];
    float* out = (float*)d_out;

    setup_pairs_kernel<<<(NPAIR_PAD + 255)/256, 256>>>();
    afm_kernel<<<BSZ, NTHREADS>>>(x, Emb, W, b, h, W1, b1, W2, b2, Wf, bf, out);
}

// round 3
// speedup vs baseline: 1.3216x; 1.0467x over previous
#include <cuda_runtime.h>
#include <cstdint>

#define TT 100
#define NPAIR 4950
#define NPAIR_PAD 4952
#define DD 32
#define AA 16
#define BSZ 1024
#define NTHREADS 128
#define MR 4
#define PSTRIDE (NTHREADS*MR)
#define EPAD 34

// pair index table: (i<<8)|j for itertools.combinations order
__device__ __align__(16) int g_pairIJ[NPAIR_PAD];

// small weights in constant memory: LDC uses the constant port, NOT the
// L1tex/smem crossbar (which round-2 ncu showed at 80.4% of peak)
__constant__ __align__(16) ulonglong2 cW2[DD*AA/4];  // W row-major, f32x2 over A (raw copy)
__constant__ float cb[AA];
__constant__ float ch[AA];
__constant__ float cW1[DD*16];
__constant__ float cb1[16];
__constant__ float cW2m[16*8];
__constant__ float cb2[8];
__constant__ float cWf[8];
__constant__ float cbf[1];

__global__ void setup_pairs_kernel() {
    int p = blockIdx.x * blockDim.x + threadIdx.x;
    if (p >= NPAIR_PAD) return;
    if (p >= NPAIR) { g_pairIJ[p] = 0; return; }
    float disc = (float)((2*TT-1)*(2*TT-1) - 8*p);
    int i = (int)(((float)(2*TT-1) - sqrtf(disc)) * 0.5f);
    if (i < 0) i = 0;
    if (i > TT-2) i = TT-2;
    while (i > 0    && (i*(2*TT-1-i))/2 > p) i--;
    while (i < TT-2 && ((i+1)*(2*TT-1-(i+1)))/2 <= p) i++;
    int off = (i*(2*TT-1-i))/2;
    int j = p - off + i + 1;
    g_pairIJ[p] = (i << 8) | j;
}

__global__ __launch_bounds__(NTHREADS, 4) void afm_kernel(
    const int*   __restrict__ x,
    const float* __restrict__ Emb,
    float* __restrict__ out)
{
    __shared__ __align__(16) float es[TT * EPAD];   // embeddings, padded rows
    __shared__ __align__(16) float att[NPAIR_PAD];  // exp(logit)
    __shared__ int   xs[TT];
    __shared__ float red[NTHREADS/32];
    __shared__ float pool4[NTHREADS/32][DD];
    __shared__ float poolv[DD];
    __shared__ float o1s[16];
    __shared__ float o2s[8];
    __shared__ float sm_isum;

    const int tid  = threadIdx.x;
    const int bidx = blockIdx.x;
    const int lane = tid & 31;
    const int wid  = tid >> 5;

    // ---- stage x indices, then gather embeddings (float2 over k) ----
    if (tid < TT) xs[tid] = x[bidx*TT + tid];
    __syncthreads();
    for (int idx = tid; idx < TT*DD/2; idx += NTHREADS) {
        int t = idx >> 4, d2 = idx & 15;
        float2 v = ((const float2*)Emb)[(size_t)xs[t] * (DD/2) + d2];
        *(float2*)&es[t*EPAD + 2*d2] = v;
    }
    __syncthreads();

    // ================= PASS 1: exp(logit) per pair =================
    // (no max-subtraction: logits are O(0.01); ratio identical)
    float lsum = 0.f;
    for (int p0 = tid*MR; p0 < NPAIR; p0 += PSTRIDE) {
        int4 pv = *((const int4*)&g_pairIJ[p0]);   // padded: safe
        int pi[MR], pj[MR];
        pi[0] = pv.x >> 8; pj[0] = pv.x & 255;
        pi[1] = pv.y >> 8; pj[1] = pv.y & 255;
        pi[2] = pv.z >> 8; pj[2] = pv.z & 255;
        pi[3] = pv.w >> 8; pj[3] = pv.w & 255;

        unsigned long long zz[MR][AA/2];
        #pragma unroll
        for (int m = 0; m < MR; m++)
            #pragma unroll
            for (int q = 0; q < AA/2; q++) zz[m][q] = 0ull;

        #pragma unroll 4
        for (int k = 0; k < DD; k += 2) {
            float2 ei[MR], ej[MR];
            #pragma unroll
            for (int m = 0; m < MR; m++) {
                ei[m] = *(const float2*)&es[pi[m]*EPAD + k];
                ej[m] = *(const float2*)&es[pj[m]*EPAD + k];
            }
            #pragma unroll
            for (int kk = 0; kk < 2; kk++) {
                // W row via LDC.128 from the constant port
                unsigned long long w2[AA/2];
                #pragma unroll
                for (int q2 = 0; q2 < AA/4; q2++) {
                    ulonglong2 t2 = cW2[(k+kk)*(AA/4) + q2];
                    w2[2*q2] = t2.x; w2[2*q2+1] = t2.y;
                }
                #pragma unroll
                for (int m = 0; m < MR; m++) {
                    float pm = kk ? (ei[m].y * ej[m].y) : (ei[m].x * ej[m].x);
                    unsigned long long pp;
                    asm("mov.b64 %0, {%1, %1};" : "=l"(pp) : "f"(pm));
                    #pragma unroll
                    for (int q = 0; q < AA/2; q++) {
                        asm("fma.rn.f32x2 %0, %1, %2, %0;"
                            : "+l"(zz[m][q]) : "l"(pp), "l"(w2[q]));
                    }
                }
            }
        }
        // bias + relu + dot(h) + exp epilogue
        #pragma unroll
        for (int m = 0; m < MR; m++) {
            float logit = 0.f;
            #pragma unroll
            for (int q = 0; q < AA/2; q++) {
                float lo, hi;
                asm("mov.b64 {%0, %1}, %2;" : "=f"(lo), "=f"(hi) : "l"(zz[m][q]));
                logit = fmaf(fmaxf(lo + cb[2*q],   0.f), ch[2*q],   logit);
                logit = fmaf(fmaxf(hi + cb[2*q+1], 0.f), ch[2*q+1], logit);
            }
            int p = p0 + m;
            if (p < NPAIR) {
                float E = __expf(logit);
                att[p] = E;
                lsum += E;
            }
        }
    }

    // ---- block reduce lsum -> 1/sum ----
    #pragma unroll
    for (int o = 16; o > 0; o >>= 1) lsum += __shfl_xor_sync(0xffffffffu, lsum, o);
    if (lane == 0) red[wid] = lsum;
    __syncthreads();
    if (tid == 0) {
        float s = 0.f;
        #pragma unroll
        for (int w = 0; w < NTHREADS/32; w++) s += red[w];
        sm_isum = 1.f / s;
    }
    if (tid < 2) att[NPAIR + tid] = 0.f;   // pad for the unrolled pass-2 tail
    __syncthreads();
    const float inv = sm_isum;

    // ================= PASS 2: attention-pooled sum =================
    float pacc = 0.f;
    for (int p = wid*2; p < NPAIR; p += (NTHREADS/32)*2) {
        int2   v2 = *(const int2*)  &g_pairIJ[p];
        float2 a2 = *(const float2*)&att[p];
        int i0 = v2.x >> 8, j0 = v2.x & 255;
        int i1 = v2.y >> 8, j1 = v2.y & 255;
        pacc = fmaf(a2.x * es[i0*EPAD + lane], es[j0*EPAD + lane], pacc);
        pacc = fmaf(a2.y * es[i1*EPAD + lane], es[j1*EPAD + lane], pacc);
    }
    pool4[wid][lane] = pacc;
    __syncthreads();
    if (tid < DD) {
        float s = 0.f;
        #pragma unroll
        for (int w = 0; w < NTHREADS/32; w++) s += pool4[w][tid];
        poolv[tid] = s * inv;
    }
    __syncthreads();

    // ================= tiny MLP (weights from constant) =================
    if (tid < 16) {
        float z = cb1[tid];
        #pragma unroll
        for (int d = 0; d < DD; d++) z = fmaf(poolv[d], cW1[d*16 + tid], z);
        o1s[tid] = fmaxf(z, 0.f);
    }
    __syncthreads();
    if (tid < 8) {
        float z = cb2[tid];
        #pragma unroll
        for (int c = 0; c < 16; c++) z = fmaf(o1s[c], cW2m[c*8 + tid], z);
        o2s[tid] = fmaxf(z, 0.f);
    }
    __syncthreads();
    if (tid == 0) {
        float z = cbf[0];
        #pragma unroll
        for (int c = 0; c < 8; c++) z = fmaf(o2s[c], cWf[c], z);
        out[bidx] = 1.f / (1.f + __expf(-z));
    }
}

extern "C" void kernel_launch(void* const* d_in, const int* in_sizes, int n_in,
                              void* d_out, int out_size) {
    const int*   x   = (const int*)  d_in[0];
    const float* Emb = (const float*)d_in[1];
    float* out = (float*)d_out;

    // stage small weights into constant memory (async D2D memcpys: graph-capturable)
    cudaMemcpyToSymbolAsync(cW2,  d_in[2],  DD*AA*sizeof(float), 0, cudaMemcpyDeviceToDevice);
    cudaMemcpyToSymbolAsync(cb,   d_in[3],  AA*sizeof(float),    0, cudaMemcpyDeviceToDevice);
    cudaMemcpyToSymbolAsync(ch,   d_in[4],  AA*sizeof(float),    0, cudaMemcpyDeviceToDevice);
    cudaMemcpyToSymbolAsync(cW1,  d_in[5],  DD*16*sizeof(float), 0, cudaMemcpyDeviceToDevice);
    cudaMemcpyToSymbolAsync(cb1,  d_in[6],  16*sizeof(float),    0, cudaMemcpyDeviceToDevice);
    cudaMemcpyToSymbolAsync(cW2m, d_in[7],  16*8*sizeof(float),  0, cudaMemcpyDeviceToDevice);
    cudaMemcpyToSymbolAsync(cb2,  d_in[8],  8*sizeof(float),     0, cudaMemcpyDeviceToDevice);
    cudaMemcpyToSymbolAsync(cWf,  d_in[9],  8*sizeof(float),     0, cudaMemcpyDeviceToDevice);
    cudaMemcpyToSymbolAsync(cbf,  d_in[10], 1*sizeof(float),     0, cudaMemcpyDeviceToDevice);

    setup_pairs_kernel<<<(NPAIR_PAD + 255)/256, 256>>>();
    afm_kernel<<<BSZ, NTHREADS>>>(x, Emb, out);
}

// round 4
// speedup vs baseline: 1.8825x; 1.4244x over previous
#include <cuda_runtime.h>
#include <cstdint>

#define TT 100
#define DD 32
#define AA 16
#define NPAIR 4950
#define NTASK 160
#define NPP (NTASK*32)      // 5120, padded pair space
#define TTP 101             // odd pad for esT2 rows
#define NTHREADS 128
#define NW (NTHREADS/32)
#define BSZ 1024

typedef unsigned long long ull;

// pair index table: (i<<8)|j for itertools.combinations order; dummies = (0,1)
__device__ __align__(16) int g_pairIJ[NPP];

// small weights in constant memory (constant port, not L1tex)
__constant__ __align__(16) ulonglong2 cW2[DD*4];   // W row-major: row k = 16 floats = 4 ulonglong2
__constant__ float cb[AA];
__constant__ float ch[AA];
__constant__ float cW1[DD*16];
__constant__ float cb1[16];
__constant__ float cW2m[16*8];
__constant__ float cb2[8];
__constant__ float cWf[8];
__constant__ float cbf[1];

__global__ void setup_pairs_kernel() {
    int p = blockIdx.x * blockDim.x + threadIdx.x;
    if (p >= NPP) return;
    if (p >= NPAIR) { g_pairIJ[p] = 1; return; }   // dummy pair (0,1)
    float disc = (float)((2*TT-1)*(2*TT-1) - 8*p);
    int i = (int)(((float)(2*TT-1) - sqrtf(disc)) * 0.5f);
    if (i < 0) i = 0;
    if (i > TT-2) i = TT-2;
    while (i > 0    && (i*(2*TT-1-i))/2 > p) i--;
    while (i < TT-2 && ((i+1)*(2*TT-1-(i+1)))/2 <= p) i++;
    int off = (i*(2*TT-1-i))/2;
    int j = p - off + i + 1;
    g_pairIJ[p] = (i << 8) | j;
}

__global__ __launch_bounds__(NTHREADS, 5) void afm_kernel(
    const int*   __restrict__ x,
    const float* __restrict__ Emb,
    float* __restrict__ out)
{
    __shared__ __align__(16) float2 esT2[AA][TTP];  // [k2][t]: dims (2k2, 2k2+1)
    __shared__ __align__(16) float att[NPP];        // exp(logit), 0 on dummies
    __shared__ int   xs[TT];
    __shared__ float red[NW];
    __shared__ float poolv[DD];
    __shared__ float o1s[16];
    __shared__ float o2s[8];
    __shared__ float sm_isum;

    const int tid  = threadIdx.x;
    const int bidx = blockIdx.x;
    const int lane = tid & 31;
    const int wid  = tid >> 5;

    // ---- stage x indices, gather embeddings transposed: esT2[d2][t] ----
    if (tid < TT) xs[tid] = x[bidx*TT + tid];
    __syncthreads();
    for (int idx = tid; idx < TT*AA; idx += NTHREADS) {
        int t = idx >> 4, d2 = idx & 15;
        float2 v = ((const float2*)Emb)[(size_t)xs[t] * AA + d2];
        esT2[d2][t] = v;
    }
    __syncthreads();

    // ================= PASS 1: exp(logit) per pair =================
    // warp-chunk = 32 consecutive pairs (lane = pair): i ~broadcast, j consecutive
    // (no max-subtraction: logits are O(0.01); softmax ratio identical)
    float lsum = 0.f;
    for (int t0 = wid*2; t0 < NTASK; t0 += NW*2) {
        const int pA = t0*32 + lane;
        const int pB = pA + 32;
        int vA = g_pairIJ[pA], vB = g_pairIJ[pB];
        int iA = vA >> 8, jA = vA & 255;
        int iB = vB >> 8, jB = vB & 255;

        ull zzA[AA/2], zzB[AA/2];
        #pragma unroll
        for (int q = 0; q < AA/2; q++) { zzA[q] = 0ull; zzB[q] = 0ull; }

        #pragma unroll
        for (int k2 = 0; k2 < AA; k2++) {
            // conflict-free LDS.64: i broadcast-ish, j lane-consecutive
            float2 eiA = esT2[k2][iA], ejA = esT2[k2][jA];
            float2 eiB = esT2[k2][iB], ejB = esT2[k2][jB];
            #pragma unroll
            for (int kk = 0; kk < 2; kk++) {
                // W row (2*k2+kk): 16 floats via 4 LDC.128, amortized over 64 pairs
                ull w2[AA/2];
                #pragma unroll
                for (int q2 = 0; q2 < 4; q2++) {
                    ulonglong2 t2 = cW2[(2*k2+kk)*4 + q2];
                    w2[2*q2] = t2.x; w2[2*q2+1] = t2.y;
                }
                float pmA = kk ? (eiA.y * ejA.y) : (eiA.x * ejA.x);
                float pmB = kk ? (eiB.y * ejB.y) : (eiB.x * ejB.x);
                ull ppA, ppB;
                asm("mov.b64 %0, {%1, %1};" : "=l"(ppA) : "f"(pmA));
                asm("mov.b64 %0, {%1, %1};" : "=l"(ppB) : "f"(pmB));
                #pragma unroll
                for (int q = 0; q < AA/2; q++) {
                    asm("fma.rn.f32x2 %0, %1, %2, %0;" : "+l"(zzA[q]) : "l"(ppA), "l"(w2[q]));
                    asm("fma.rn.f32x2 %0, %1, %2, %0;" : "+l"(zzB[q]) : "l"(ppB), "l"(w2[q]));
                }
            }
        }
        // bias + relu + dot(h) + exp epilogue; coalesced att store
        float logitA = 0.f, logitB = 0.f;
        #pragma unroll
        for (int q = 0; q < AA/2; q++) {
            float loA, hiA, loB, hiB;
            asm("mov.b64 {%0, %1}, %2;" : "=f"(loA), "=f"(hiA) : "l"(zzA[q]));
            asm("mov.b64 {%0, %1}, %2;" : "=f"(loB), "=f"(hiB) : "l"(zzB[q]));
            logitA = fmaf(fmaxf(loA + cb[2*q],   0.f), ch[2*q],   logitA);
            logitA = fmaf(fmaxf(hiA + cb[2*q+1], 0.f), ch[2*q+1], logitA);
            logitB = fmaf(fmaxf(loB + cb[2*q],   0.f), ch[2*q],   logitB);
            logitB = fmaf(fmaxf(hiB + cb[2*q+1], 0.f), ch[2*q+1], logitB);
        }
        float EA = (pA < NPAIR) ? __expf(logitA) : 0.f;
        float EB = (pB < NPAIR) ? __expf(logitB) : 0.f;
        att[pA] = EA;
        att[pB] = EB;
        lsum += EA + EB;
    }

    // ---- block reduce lsum -> 1/sum ----
    #pragma unroll
    for (int o = 16; o > 0; o >>= 1) lsum += __shfl_xor_sync(0xffffffffu, lsum, o);
    if (lane == 0) red[wid] = lsum;
    __syncthreads();
    if (tid == 0) {
        float s = 0.f;
        #pragma unroll
        for (int w = 0; w < NW; w++) s += red[w];
        sm_isum = 1.f / s;
    }
    __syncthreads();
    const float inv = sm_isum;

    // ================= PASS 2: attention-pooled sum (transposed layout) ======
    // warp owns 4 float2-dims (d2 = wid*4+q); lanes stream 32 consecutive pairs
    {
        ull acc[4];
        #pragma unroll
        for (int q = 0; q < 4; q++) acc[q] = 0ull;
        const int d2base = wid * 4;

        for (int p0 = 0; p0 < NPP; p0 += 32) {
            int v = g_pairIJ[p0 + lane];
            float a = att[p0 + lane];          // coalesced LDS; 0 on dummies
            int i = v >> 8, j = v & 255;
            ull aa;
            asm("mov.b64 %0, {%1, %1};" : "=l"(aa) : "f"(a));
            #pragma unroll
            for (int q = 0; q < 4; q++) {
                ull vi = *(const ull*)&esT2[d2base + q][i];  // broadcast-ish
                ull vj = *(const ull*)&esT2[d2base + q][j];  // consecutive
                ull prod;
                asm("mul.rn.f32x2 %0, %1, %2;" : "=l"(prod) : "l"(vi), "l"(vj));
                asm("fma.rn.f32x2 %0, %1, %2, %0;" : "+l"(acc[q]) : "l"(aa), "l"(prod));
            }
        }
        // warp-reduce 8 floats, lane 0 writes poolv (already scaled by inv)
        #pragma unroll
        for (int q = 0; q < 4; q++) {
            float lo, hi;
            asm("mov.b64 {%0, %1}, %2;" : "=f"(lo), "=f"(hi) : "l"(acc[q]));
            #pragma unroll
            for (int o = 16; o > 0; o >>= 1) {
                lo += __shfl_xor_sync(0xffffffffu, lo, o);
                hi += __shfl_xor_sync(0xffffffffu, hi, o);
            }
            if (lane == 0) {
                poolv[2*(d2base+q)]   = lo * inv;
                poolv[2*(d2base+q)+1] = hi * inv;
            }
        }
    }
    __syncthreads();

    // ================= tiny MLP (weights from constant) =================
    if (tid < 16) {
        float z = cb1[tid];
        #pragma unroll
        for (int d = 0; d < DD; d++) z = fmaf(poolv[d], cW1[d*16 + tid], z);
        o1s[tid] = fmaxf(z, 0.f);
    }
    __syncthreads();
    if (tid < 8) {
        float z = cb2[tid];
        #pragma unroll
        for (int c = 0; c < 16; c++) z = fmaf(o1s[c], cW2m[c*8 + tid], z);
        o2s[tid] = fmaxf(z, 0.f);
    }
    __syncthreads();
    if (tid == 0) {
        float z = cbf[0];
        #pragma unroll
        for (int c = 0; c < 8; c++) z = fmaf(o2s[c], cWf[c], z);
        out[bidx] = 1.f / (1.f + __expf(-z));
    }
}

extern "C" void kernel_launch(void* const* d_in, const int* in_sizes, int n_in,
                              void* d_out, int out_size) {
    const int*   x   = (const int*)  d_in[0];
    const float* Emb = (const float*)d_in[1];
    float* out = (float*)d_out;

    // stage small weights into constant memory (async D2D: graph-capturable)
    cudaMemcpyToSymbolAsync(cW2,  d_in[2],  DD*AA*sizeof(float), 0, cudaMemcpyDeviceToDevice);
    cudaMemcpyToSymbolAsync(cb,   d_in[3],  AA*sizeof(float),    0, cudaMemcpyDeviceToDevice);
    cudaMemcpyToSymbolAsync(ch,   d_in[4],  AA*sizeof(float),    0, cudaMemcpyDeviceToDevice);
    cudaMemcpyToSymbolAsync(cW1,  d_in[5],  DD*16*sizeof(float), 0, cudaMemcpyDeviceToDevice);
    cudaMemcpyToSymbolAsync(cb1,  d_in[6],  16*sizeof(float),    0, cudaMemcpyDeviceToDevice);
    cudaMemcpyToSymbolAsync(cW2m, d_in[7],  16*8*sizeof(float),  0, cudaMemcpyDeviceToDevice);
    cudaMemcpyToSymbolAsync(cb2,  d_in[8],  8*sizeof(float),     0, cudaMemcpyDeviceToDevice);
    cudaMemcpyToSymbolAsync(cWf,  d_in[9],  8*sizeof(float),     0, cudaMemcpyDeviceToDevice);
    cudaMemcpyToSymbolAsync(cbf,  d_in[10], 1*sizeof(float),     0, cudaMemcpyDeviceToDevice);

    setup_pairs_kernel<<<(NPP + 255)/256, 256>>>();
    afm_kernel<<<BSZ, NTHREADS>>>(x, Emb, out);
}

// round 5
// speedup vs baseline: 1.8907x; 1.0043x over previous
#include <cuda_runtime.h>
#include <cstdint>

#define TT 100
#define DD 32
#define AA 16
#define NPAIR 4950
#define NTASK 160
#define NPP (NTASK*32)      // 5120, padded pair space
#define TTP 101             // odd pad for esT2 rows
#define NTHREADS 128
#define NW (NTHREADS/32)
#define BSZ 1024

typedef unsigned long long ull;

// pair index table: (i<<8)|j for itertools.combinations order; dummies = (0,1)
__device__ __align__(16) int g_pairIJ[NPP];

// small weights in constant memory (constant port, not L1tex)
__constant__ __align__(16) ulonglong2 cW2[DD*4];   // W row-major: row k = 16 floats = 4 ulonglong2
__constant__ float cb[AA];
__constant__ float ch[AA];
__constant__ float cW1[DD*16];
__constant__ float cb1[16];
__constant__ float cW2m[16*8];
__constant__ float cb2[8];
__constant__ float cWf[8];
__constant__ float cbf[1];

__global__ void setup_pairs_kernel() {
    int p = blockIdx.x * blockDim.x + threadIdx.x;
    if (p >= NPP) return;
    if (p >= NPAIR) { g_pairIJ[p] = 1; return; }   // dummy pair (0,1)
    float disc = (float)((2*TT-1)*(2*TT-1) - 8*p);
    int i = (int)(((float)(2*TT-1) - sqrtf(disc)) * 0.5f);
    if (i < 0) i = 0;
    if (i > TT-2) i = TT-2;
    while (i > 0    && (i*(2*TT-1-i))/2 > p) i--;
    while (i < TT-2 && ((i+1)*(2*TT-1-(i+1)))/2 <= p) i++;
    int off = (i*(2*TT-1-i))/2;
    int j = p - off + i + 1;
    g_pairIJ[p] = (i << 8) | j;
}

__global__ __launch_bounds__(NTHREADS, 5) void afm_kernel(
    const int*   __restrict__ x,
    const float* __restrict__ Emb,
    float* __restrict__ out)
{
    __shared__ __align__(16) float2 esT2[AA][TTP];  // [k2][t]: dims (2k2, 2k2+1)
    __shared__ __align__(16) float att[NPP];        // exp(logit), 0 on dummies
    __shared__ int   xs[TT];
    __shared__ float red[NW];
    __shared__ float poolv[DD];
    __shared__ float o1s[16];
    __shared__ float o2s[8];
    __shared__ float sm_isum;

    const int tid  = threadIdx.x;
    const int bidx = blockIdx.x;
    const int lane = tid & 31;
    const int wid  = tid >> 5;

    // ---- stage x indices, gather embeddings transposed: esT2[d2][t] ----
    if (tid < TT) xs[tid] = x[bidx*TT + tid];
    __syncthreads();
    for (int idx = tid; idx < TT*AA; idx += NTHREADS) {
        int t = idx >> 4, d2 = idx & 15;
        float2 v = ((const float2*)Emb)[(size_t)xs[t] * AA + d2];
        esT2[d2][t] = v;
    }
    __syncthreads();

    // ================= PASS 1: exp(logit) per pair =================
    // warp-chunk = 32 consecutive pairs (lane = pair): i ~broadcast, j consecutive
    // (no max-subtraction: logits are O(0.01); softmax ratio identical)
    float lsum = 0.f;
    for (int t0 = wid*2; t0 < NTASK; t0 += NW*2) {
        const int pA = t0*32 + lane;
        const int pB = pA + 32;
        int vA = g_pairIJ[pA], vB = g_pairIJ[pB];
        int iA = vA >> 8, jA = vA & 255;
        int iB = vB >> 8, jB = vB & 255;

        ull zzA[AA/2], zzB[AA/2];
        #pragma unroll
        for (int q = 0; q < AA/2; q++) { zzA[q] = 0ull; zzB[q] = 0ull; }

        #pragma unroll
        for (int k2 = 0; k2 < AA; k2++) {
            // conflict-free LDS.64: i broadcast-ish, j lane-consecutive
            float2 eiA = esT2[k2][iA], ejA = esT2[k2][jA];
            float2 eiB = esT2[k2][iB], ejB = esT2[k2][jB];
            #pragma unroll
            for (int kk = 0; kk < 2; kk++) {
                // W row (2*k2+kk): 16 floats via 4 LDC.128, amortized over 64 pairs
                ull w2[AA/2];
                #pragma unroll
                for (int q2 = 0; q2 < 4; q2++) {
                    ulonglong2 t2 = cW2[(2*k2+kk)*4 + q2];
                    w2[2*q2] = t2.x; w2[2*q2+1] = t2.y;
                }
                float pmA = kk ? (eiA.y * ejA.y) : (eiA.x * ejA.x);
                float pmB = kk ? (eiB.y * ejB.y) : (eiB.x * ejB.x);
                ull ppA, ppB;
                asm("mov.b64 %0, {%1, %1};" : "=l"(ppA) : "f"(pmA));
                asm("mov.b64 %0, {%1, %1};" : "=l"(ppB) : "f"(pmB));
                #pragma unroll
                for (int q = 0; q < AA/2; q++) {
                    asm("fma.rn.f32x2 %0, %1, %2, %0;" : "+l"(zzA[q]) : "l"(ppA), "l"(w2[q]));
                    asm("fma.rn.f32x2 %0, %1, %2, %0;" : "+l"(zzB[q]) : "l"(ppB), "l"(w2[q]));
                }
            }
        }
        // bias + relu + dot(h) + exp epilogue; coalesced att store
        float logitA = 0.f, logitB = 0.f;
        #pragma unroll
        for (int q = 0; q < AA/2; q++) {
            float loA, hiA, loB, hiB;
            asm("mov.b64 {%0, %1}, %2;" : "=f"(loA), "=f"(hiA) : "l"(zzA[q]));
            asm("mov.b64 {%0, %1}, %2;" : "=f"(loB), "=f"(hiB) : "l"(zzB[q]));
            logitA = fmaf(fmaxf(loA + cb[2*q],   0.f), ch[2*q],   logitA);
            logitA = fmaf(fmaxf(hiA + cb[2*q+1], 0.f), ch[2*q+1], logitA);
            logitB = fmaf(fmaxf(loB + cb[2*q],   0.f), ch[2*q],   logitB);
            logitB = fmaf(fmaxf(hiB + cb[2*q+1], 0.f), ch[2*q+1], logitB);
        }
        float EA = (pA < NPAIR) ? __expf(logitA) : 0.f;
        float EB = (pB < NPAIR) ? __expf(logitB) : 0.f;
        att[pA] = EA;
        att[pB] = EB;
        lsum += EA + EB;
    }

    // ---- block reduce lsum -> 1/sum ----
    #pragma unroll
    for (int o = 16; o > 0; o >>= 1) lsum += __shfl_xor_sync(0xffffffffu, lsum, o);
    if (lane == 0) red[wid] = lsum;
    __syncthreads();
    if (tid == 0) {
        float s = 0.f;
        #pragma unroll
        for (int w = 0; w < NW; w++) s += red[w];
        sm_isum = 1.f / s;
    }
    __syncthreads();
    const float inv = sm_isum;

    // ================= PASS 2: attention-pooled sum (transposed layout) ======
    // warp owns 4 float2-dims (d2 = wid*4+q); lanes stream 32 consecutive pairs
    {
        ull acc[4];
        #pragma unroll
        for (int q = 0; q < 4; q++) acc[q] = 0ull;
        const int d2base = wid * 4;

        for (int p0 = 0; p0 < NPP; p0 += 32) {
            int v = g_pairIJ[p0 + lane];
            float a = att[p0 + lane];          // coalesced LDS; 0 on dummies
            int i = v >> 8, j = v & 255;
            ull aa;
            asm("mov.b64 %0, {%1, %1};" : "=l"(aa) : "f"(a));
            #pragma unroll
            for (int q = 0; q < 4; q++) {
                ull vi = *(const ull*)&esT2[d2base + q][i];  // broadcast-ish
                ull vj = *(const ull*)&esT2[d2base + q][j];  // consecutive
                ull prod;
                asm("mul.rn.f32x2 %0, %1, %2;" : "=l"(prod) : "l"(vi), "l"(vj));
                asm("fma.rn.f32x2 %0, %1, %2, %0;" : "+l"(acc[q]) : "l"(aa), "l"(prod));
            }
        }
        // warp-reduce 8 floats, lane 0 writes poolv (already scaled by inv)
        #pragma unroll
        for (int q = 0; q < 4; q++) {
            float lo, hi;
            asm("mov.b64 {%0, %1}, %2;" : "=f"(lo), "=f"(hi) : "l"(acc[q]));
            #pragma unroll
            for (int o = 16; o > 0; o >>= 1) {
                lo += __shfl_xor_sync(0xffffffffu, lo, o);
                hi += __shfl_xor_sync(0xffffffffu, hi, o);
            }
            if (lane == 0) {
                poolv[2*(d2base+q)]   = lo * inv;
                poolv[2*(d2base+q)+1] = hi * inv;
            }
        }
    }
    __syncthreads();

    // ================= tiny MLP (weights from constant) =================
    if (tid < 16) {
        float z = cb1[tid];
        #pragma unroll
        for (int d = 0; d < DD; d++) z = fmaf(poolv[d], cW1[d*16 + tid], z);
        o1s[tid] = fmaxf(z, 0.f);
    }
    __syncthreads();
    if (tid < 8) {
        float z = cb2[tid];
        #pragma unroll
        for (int c = 0; c < 16; c++) z = fmaf(o1s[c], cW2m[c*8 + tid], z);
        o2s[tid] = fmaxf(z, 0.f);
    }
    __syncthreads();
    if (tid == 0) {
        float z = cbf[0];
        #pragma unroll
        for (int c = 0; c < 8; c++) z = fmaf(o2s[c], cWf[c], z);
        out[bidx] = 1.f / (1.f + __expf(-z));
    }
}

extern "C" void kernel_launch(void* const* d_in, const int* in_sizes, int n_in,
                              void* d_out, int out_size) {
    const int*   x   = (const int*)  d_in[0];
    const float* Emb = (const float*)d_in[1];
    float* out = (float*)d_out;

    // stage small weights into constant memory (async D2D: graph-capturable)
    cudaMemcpyToSymbolAsync(cW2,  d_in[2],  DD*AA*sizeof(float), 0, cudaMemcpyDeviceToDevice);
    cudaMemcpyToSymbolAsync(cb,   d_in[3],  AA*sizeof(float),    0, cudaMemcpyDeviceToDevice);
    cudaMemcpyToSymbolAsync(ch,   d_in[4],  AA*sizeof(float),    0, cudaMemcpyDeviceToDevice);
    cudaMemcpyToSymbolAsync(cW1,  d_in[5],  DD*16*sizeof(float), 0, cudaMemcpyDeviceToDevice);
    cudaMemcpyToSymbolAsync(cb1,  d_in[6],  16*sizeof(float),    0, cudaMemcpyDeviceToDevice);
    cudaMemcpyToSymbolAsync(cW2m, d_in[7],  16*8*sizeof(float),  0, cudaMemcpyDeviceToDevice);
    cudaMemcpyToSymbolAsync(cb2,  d_in[8],  8*sizeof(float),     0, cudaMemcpyDeviceToDevice);
    cudaMemcpyToSymbolAsync(cWf,  d_in[9],  8*sizeof(float),     0, cudaMemcpyDeviceToDevice);
    cudaMemcpyToSymbolAsync(cbf,  d_in[10], 1*sizeof(float),     0, cudaMemcpyDeviceToDevice);

    setup_pairs_kernel<<<(NPP + 255)/256, 256>>>();
    afm_kernel<<<BSZ, NTHREADS>>>(x, Emb, out);
}